// round 13
// baseline (speedup 1.0000x reference)
#include <cuda_runtime.h>
#include <cuda_fp16.h>
#include <math.h>
#include <stdint.h>

#define NROWS 4096
#define BHALF 2048
#define D     1024
#define C     12
#define BM    128
#define BN    256
#define NT_J  16                    // 256-wide col blocks
#define NBLK  272                   // triangular-covering 128x256 blocks
#define NPERS 148
#define KCH   32
#define NCH   (D / KCH)             // 32
#define RSTR  40                    // fp16 row stride in halves

#define SZ_AHI (BM * RSTR * 2)      // 10240
#define SZ_BHI (BN * RSTR * 2)      // 20480
#define BUFSZ  (2 * SZ_AHI + 2 * SZ_BHI)   // 61440
#define OFF_AHI 0
#define OFF_ALO (SZ_AHI)
#define OFF_BHI (2 * SZ_AHI)
#define OFF_BLO (2 * SZ_AHI + SZ_BHI)
#define OFF_ZB  (2 * BUFSZ)                 // 122880
#define OFF_SQB (OFF_ZB + BN * C * 4)       // +12288
#define SMEM_REQ (OFF_SQB + BN * 4 + 256)   // ~136.5KB

// ---- scratch ----
__device__ __half g_hi[(size_t)NROWS * D];
__device__ __half g_lo[(size_t)NROWS * D];
__device__ float  g_sq[NROWS];
__device__ float  g_colpart[128][D];
__device__ float  g_cpart[128][C];
__device__ int    g_prespart[128];
__device__ float  g_fac[2 * C];
__device__ double g_loss;
__device__ float  g_coef;
__device__ int    g_pctr;
__device__ int    g_tilectr;
__device__ int    g_donectr;

static __device__ __forceinline__ uint32_t s2u(const void* p) {
    uint32_t a;
    asm("{ .reg .u64 t; cvta.to.shared.u64 t, %1; cvt.u32.u64 %0, t; }" : "=r"(a) : "l"(p));
    return a;
}

#define CP_ASYNC16(dst, src) \
    asm volatile("cp.async.cg.shared.global [%0], [%1], 16;" :: "r"(dst), "l"(src))
#define CP_COMMIT()  asm volatile("cp.async.commit_group;" ::: "memory")
#define CP_WAIT1()   asm volatile("cp.async.wait_group 1;" ::: "memory")
#define CP_WAIT0()   asm volatile("cp.async.wait_group 0;" ::: "memory")

#define LDSM4(r, a) \
    asm volatile("ldmatrix.sync.aligned.m8n8.x4.shared.b16 {%0,%1,%2,%3}, [%4];" \
        : "=r"((r)[0]), "=r"((r)[1]), "=r"((r)[2]), "=r"((r)[3]) : "r"(a))

static __device__ __forceinline__ void mma_f16(float* c, const uint32_t* a,
                                               uint32_t b0, uint32_t b1) {
    asm volatile(
        "mma.sync.aligned.m16n8k16.row.col.f32.f16.f16.f32 "
        "{%0,%1,%2,%3}, {%4,%5,%6,%7}, {%8,%9}, {%0,%1,%2,%3};"
        : "+f"(c[0]), "+f"(c[1]), "+f"(c[2]), "+f"(c[3])
        : "r"(a[0]), "r"(a[1]), "r"(a[2]), "r"(a[3]), "r"(b0), "r"(b1));
}

// ============== launch 0: fused labels + split + row-sq + colsum + finalize
__global__ void k_prep(const float* __restrict__ src, const float* __restrict__ tgt,
                       const float* __restrict__ sl,  const float* __restrict__ tl) {
    __shared__ float scol[D];
    __shared__ double dr[256];
    __shared__ int lastf;
    const int tid = threadIdx.x, lane = tid & 31, w = tid >> 5;
    const int bid = blockIdx.x;
    const int r0 = bid * 32;
    const bool isSrc = (r0 < BHALF);
    const float* base = isSrc ? src + (size_t)r0 * D : tgt + (size_t)(r0 - BHALF) * D;

    for (int c = tid; c < D; c += 256) scol[c] = 0.f;

    if (w == 0) {
        const float* lp = isSrc ? sl + (size_t)(r0 + lane) * C
                                : tl + (size_t)(r0 - BHALF + lane) * C;
        float v[C];
        float4 q0 = *(const float4*)lp;
        float4 q1 = *(const float4*)(lp + 4);
        float4 q2 = *(const float4*)(lp + 8);
        v[0] = q0.x; v[1] = q0.y; v[2]  = q0.z; v[3]  = q0.w;
        v[4] = q1.x; v[5] = q1.y; v[6]  = q1.z; v[7]  = q1.w;
        v[8] = q2.x; v[9] = q2.y; v[10] = q2.z; v[11] = q2.w;
        int arg = 0; float best = v[0];
        #pragma unroll
        for (int c = 1; c < C; c++) if (v[c] > best) { best = v[c]; arg = c; }
        unsigned pres = __reduce_or_sync(0xffffffffu, 1u << arg);
        #pragma unroll
        for (int c = 0; c < C; c++) {
            #pragma unroll
            for (int o = 16; o > 0; o >>= 1)
                v[c] += __shfl_xor_sync(0xffffffffu, v[c], o);
        }
        if (lane == 0) {
            #pragma unroll
            for (int c = 0; c < C; c++) g_cpart[bid][c] = v[c];
            g_prespart[bid] = (int)pres;
        }
    }
    __syncthreads();

    float4 csum[8];
    #pragma unroll
    for (int j = 0; j < 8; j++) csum[j] = make_float4(0.f, 0.f, 0.f, 0.f);
    #pragma unroll
    for (int t = 0; t < 4; t++) {
        const int rr = w + 8 * t;
        const float* p = base + (size_t)rr * D;
        __half* ph = g_hi + (size_t)(r0 + rr) * D;
        __half* pl = g_lo + (size_t)(r0 + rr) * D;
        float sq = 0.f;
        #pragma unroll
        for (int j = 0; j < 8; j++) {
            const int col = lane * 4 + 128 * j;
            float4 v = *(const float4*)(p + col);
            sq += v.x * v.x + v.y * v.y + v.z * v.z + v.w * v.w;
            csum[j].x += v.x; csum[j].y += v.y; csum[j].z += v.z; csum[j].w += v.w;
            __half h[4], l[4];
            float vv[4] = {v.x, v.y, v.z, v.w};
            #pragma unroll
            for (int q = 0; q < 4; q++) {
                h[q] = __float2half_rn(vv[q]);
                l[q] = __float2half_rn(vv[q] - __half2float(h[q]));
            }
            *(uint2*)(ph + col) = *(uint2*)h;
            *(uint2*)(pl + col) = *(uint2*)l;
        }
        #pragma unroll
        for (int o = 16; o > 0; o >>= 1) sq += __shfl_xor_sync(0xffffffffu, sq, o);
        if (lane == 0) g_sq[r0 + rr] = sq;
    }
    #pragma unroll
    for (int j = 0; j < 8; j++) {
        const int col = lane * 4 + 128 * j;
        atomicAdd(&scol[col + 0], csum[j].x);
        atomicAdd(&scol[col + 1], csum[j].y);
        atomicAdd(&scol[col + 2], csum[j].z);
        atomicAdd(&scol[col + 3], csum[j].w);
    }
    __syncthreads();
    #pragma unroll
    for (int q = 0; q < 4; q++) {
        const int c = tid + 256 * q;
        g_colpart[bid][c] = scol[c];
    }
    __threadfence();
    __syncthreads();
    if (tid == 0) lastf = (atomicAdd(&g_pctr, 1) == 127) ? 1 : 0;
    __syncthreads();
    if (!lastf) return;

    if (tid < C) {
        float ss = 0.f, ts = 0.f;
        int sp = 0, tp = 0;
        for (int b = 0; b < 64; b++)   { ss += g_cpart[b][tid]; sp |= g_prespart[b]; }
        for (int b = 64; b < 128; b++) { ts += g_cpart[b][tid]; tp |= g_prespart[b]; }
        bool common = ((sp >> tid) & 1) && ((tp >> tid) & 1);
        g_fac[tid]     = (common && ss > 0.f) ?  1.f / ss : 0.f;
        g_fac[C + tid] = (common && ts > 0.f) ? -1.f / ts : 0.f;
    }
    double s = 0.0;
    for (int i = tid; i < NROWS; i += 256) s += (double)g_sq[i];
    dr[tid] = s;
    __syncthreads();
    for (int o = 128; o > 0; o >>= 1) {
        if (tid < o) dr[tid] += dr[tid + o];
        __syncthreads();
    }
    double sumsq = dr[0];
    __syncthreads();
    s = 0.0;
    for (int c = tid; c < D; c += 256) {
        float cs = 0.f;
        for (int b = 0; b < 128; b++) cs += g_colpart[b][c];
        s += (double)cs * (double)cs;
    }
    dr[tid] = s;
    __syncthreads();
    for (int o = 128; o > 0; o >>= 1) {
        if (tid < o) dr[tid] += dr[tid + o];
        __syncthreads();
    }
    if (tid == 0) {
        const double n = (double)NROWS;
        double sum_l2 = 2.0 * n * sumsq - 2.0 * dr[0];
        double bw = sum_l2 / (n * n - n) / 4.0;
        g_coef = (float)(-1.0 / (16.0 * bw * 0.6931471805599453));
        g_loss = 0.0;
        g_tilectr = 0;
        g_donectr = 0;
        g_pctr = 0;
    }
}

// ============== launch 1: persistent 512-thread fp16-split MMA, 128x256 tiles
__global__ __launch_bounds__(512, 1) void k_mmd(const float* __restrict__ sl,
                                                const float* __restrict__ tl,
                                                float* __restrict__ out) {
    extern __shared__ __align__(16) unsigned char sm[];
    float* zB  = (float*)(sm + OFF_ZB);
    float* sqB = (float*)(sm + OFF_SQB);
    __shared__ float red[16];
    __shared__ float s_fac[2 * C];
    __shared__ int s_tile;

    const int tid = threadIdx.x, wid = tid >> 5, lane = tid & 31;
    const int wm = wid >> 2, wn = wid & 3;           // warp grid 4m x 4n, warp = 32x64
    const int gq = lane >> 2, gr = lane & 3;
    const uint32_t smU = s2u(sm);

    if (tid < 2 * C) s_fac[tid] = g_fac[tid];

    // cp.async staging map (512 threads)
    const int srow = tid >> 2, sseg = tid & 3;       // A: 1 task; B: 2 tasks
    const uint32_t sAH = smU + OFF_AHI + (srow * RSTR + sseg * 8) * 2;
    const uint32_t sAL = smU + OFF_ALO + (srow * RSTR + sseg * 8) * 2;
    const uint32_t sBH0 = smU + OFF_BHI + (srow * RSTR + sseg * 8) * 2;
    const uint32_t sBH1 = smU + OFF_BHI + ((srow + 128) * RSTR + sseg * 8) * 2;
    const uint32_t sBL0 = smU + OFF_BLO + (srow * RSTR + sseg * 8) * 2;
    const uint32_t sBL1 = smU + OFF_BLO + ((srow + 128) * RSTR + sseg * 8) * 2;

    // ldmatrix lane offsets
    const uint32_t aoffH = (((uint32_t)(wm * 32 + (lane & 15))) * RSTR + (lane >> 4) * 8) * 2;
    const uint32_t boffH = (((uint32_t)(wn * 64 + (lane & 7) + ((lane >> 4) * 8))) * RSTR
                           + ((lane >> 3) & 1) * 8) * 2;

    while (true) {
        if (tid == 0) s_tile = atomicAdd(&g_tilectr, 1);
        __syncthreads();
        const int T = s_tile;
        if (T >= NBLK) break;

        // decode 128x256 block (bi: 128-row, bj2: 256-col, bj2 >= bi/2)
        int L = T, bi = 0;
        while (L >= NT_J - (bi >> 1)) { L -= NT_J - (bi >> 1); bi++; }
        const int bj2 = (bi >> 1) + L;
        const int rowA = bi * BM, rowB = bj2 * BN;
        const size_t gA = (size_t)rowA * D, gB = (size_t)rowB * D;

        const __half* pAH = g_hi + gA + (size_t)srow * D + sseg * 8;
        const __half* pAL = g_lo + gA + (size_t)srow * D + sseg * 8;
        const __half* pBH0 = g_hi + gB + (size_t)srow * D + sseg * 8;
        const __half* pBH1 = pBH0 + (size_t)128 * D;
        const __half* pBL0 = g_lo + gB + (size_t)srow * D + sseg * 8;
        const __half* pBL1 = pBL0 + (size_t)128 * D;

    #define STAGE(bo, ko) do {                      \
        CP_ASYNC16(sAH + (bo), pAH + (ko));         \
        CP_ASYNC16(sAL + (bo), pAL + (ko));         \
        CP_ASYNC16(sBH0 + (bo), pBH0 + (ko));       \
        CP_ASYNC16(sBH1 + (bo), pBH1 + (ko));       \
        CP_ASYNC16(sBL0 + (bo), pBL0 + (ko));       \
        CP_ASYNC16(sBL1 + (bo), pBL1 + (ko));       \
        CP_COMMIT();                                \
    } while (0)

        STAGE(0, 0);

        // stage zB / sqB for the 256 B rows
        for (int t = tid; t < BN * C; t += 512) {
            const int r = rowB + t / C, c = t % C;
            zB[t] = (r < BHALF) ? sl[(size_t)r * C + c] * s_fac[c]
                                : tl[(size_t)(r - BHALF) * C + c] * s_fac[C + c];
        }
        if (tid < BN) sqB[tid] = g_sq[rowB + tid];

        float acc[2][8][4];
        #pragma unroll
        for (int m = 0; m < 2; m++)
            #pragma unroll
            for (int n = 0; n < 8; n++)
                #pragma unroll
                for (int r = 0; r < 4; r++) acc[m][n][r] = 0.f;

        for (int c = 0; c < NCH; c++) {
            const int buf = c & 1;
            if (c + 1 < NCH) { STAGE((uint32_t)(buf ^ 1) * BUFSZ, (size_t)(c + 1) * KCH); CP_WAIT1(); }
            else             { CP_WAIT0(); }
            __syncthreads();

            const uint32_t bo = (uint32_t)buf * BUFSZ;
            const uint32_t aHi = smU + bo + OFF_AHI + aoffH;
            const uint32_t aLo = smU + bo + OFF_ALO + aoffH;
            const uint32_t bHi = smU + bo + OFF_BHI + boffH;
            const uint32_t bLo = smU + bo + OFF_BLO + boffH;

            #pragma unroll
            for (int ks = 0; ks < 2; ks++) {
                const uint32_t kso = ks * 32;
                uint32_t ahi[2][4], alo[2][4];
                LDSM4(ahi[0], aHi + kso);
                LDSM4(ahi[1], aHi + kso + 16 * RSTR * 2);
                LDSM4(alo[0], aLo + kso);
                LDSM4(alo[1], aLo + kso + 16 * RSTR * 2);
                #pragma unroll
                for (int nb = 0; nb < 4; nb++) {
                    const uint32_t nbo = kso + nb * 16 * RSTR * 2;
                    uint32_t bh[4], bl[4];
                    LDSM4(bh, bHi + nbo);
                    LDSM4(bl, bLo + nbo);
                    const int n0 = 2 * nb, n1 = 2 * nb + 1;
                    mma_f16(acc[0][n0], ahi[0], bh[0], bh[1]);
                    mma_f16(acc[1][n0], ahi[1], bh[0], bh[1]);
                    mma_f16(acc[0][n1], ahi[0], bh[2], bh[3]);
                    mma_f16(acc[1][n1], ahi[1], bh[2], bh[3]);
                    mma_f16(acc[0][n0], alo[0], bh[0], bh[1]);
                    mma_f16(acc[1][n0], alo[1], bh[0], bh[1]);
                    mma_f16(acc[0][n1], alo[0], bh[2], bh[3]);
                    mma_f16(acc[1][n1], alo[1], bh[2], bh[3]);
                    mma_f16(acc[0][n0], ahi[0], bl[0], bl[1]);
                    mma_f16(acc[1][n0], ahi[1], bl[0], bl[1]);
                    mma_f16(acc[0][n1], ahi[0], bl[2], bl[3]);
                    mma_f16(acc[1][n1], ahi[1], bl[2], bl[3]);
                }
            }
            __syncthreads();
        }

        // ---- epilogue: per-element triangular mask ----
        const float coef = g_coef;
        float lsum = 0.f;
        #pragma unroll
        for (int m = 0; m < 2; m++) {
            #pragma unroll
            for (int h = 0; h < 2; h++) {
                const int ig = rowA + wm * 32 + m * 16 + gq + 8 * h;
                const float sqi = g_sq[ig];
                const float* zp = (ig < BHALF) ? sl + (size_t)ig * C
                                               : tl + (size_t)(ig - BHALF) * C;
                const int fo = (ig < BHALF) ? 0 : C;
                float zi[C];
                {
                    float4 q0 = *(const float4*)zp;
                    float4 q1 = *(const float4*)(zp + 4);
                    float4 q2 = *(const float4*)(zp + 8);
                    zi[0]  = q0.x * s_fac[fo + 0];  zi[1]  = q0.y * s_fac[fo + 1];
                    zi[2]  = q0.z * s_fac[fo + 2];  zi[3]  = q0.w * s_fac[fo + 3];
                    zi[4]  = q1.x * s_fac[fo + 4];  zi[5]  = q1.y * s_fac[fo + 5];
                    zi[6]  = q1.z * s_fac[fo + 6];  zi[7]  = q1.w * s_fac[fo + 7];
                    zi[8]  = q2.x * s_fac[fo + 8];  zi[9]  = q2.y * s_fac[fo + 9];
                    zi[10] = q2.z * s_fac[fo + 10]; zi[11] = q2.w * s_fac[fo + 11];
                }
                #pragma unroll
                for (int n = 0; n < 8; n++) {
                    #pragma unroll
                    for (int p = 0; p < 2; p++) {
                        const int jl = wn * 64 + n * 8 + 2 * gr + p;
                        const int jg = rowB + jl;
                        const float gv = acc[m][n][2 * h + p];
                        float l2 = fmaxf(fmaf(-2.f, gv, sqi + sqB[jl]), 0.f);
                        float e;
                        asm("ex2.approx.ftz.f32 %0, %1;" : "=f"(e) : "f"(l2 * coef));
                        float e2 = e * e, e4 = e2 * e2, e8 = e4 * e4, e16 = e8 * e8;
                        float ks5 = e + e2 + e4 + e8 + e16;
                        float w = 0.f;
                        #pragma unroll
                        for (int cc = 0; cc < C; cc++) w = fmaf(zi[cc], zB[jl * C + cc], w);
                        const float sc = (jg > ig) ? 2.f : ((jg == ig) ? 1.f : 0.f);
                        lsum = fmaf(sc * w, ks5, lsum);
                    }
                }
            }
        }

        #pragma unroll
        for (int o = 16; o > 0; o >>= 1) lsum += __shfl_xor_sync(0xffffffffu, lsum, o);
        if (lane == 0) red[wid] = lsum;
        __syncthreads();
        if (tid == 0) {
            float s = 0.f;
            #pragma unroll
            for (int w = 0; w < 16; w++) s += red[w];
            atomicAdd(&g_loss, (double)s);
        }
    }

    if (tid == 0) {
        __threadfence();
        int d = atomicAdd(&g_donectr, 1);
        if (d == (int)gridDim.x - 1) {
            float f = (float)(g_loss / 12.0);
            if (!isfinite(f)) f = 0.f;
            out[0] = f;
        }
    }
}

// ================================================================ launch
extern "C" void kernel_launch(void* const* d_in, const int* in_sizes, int n_in,
                              void* d_out, int out_size) {
    const float* src = (const float*)d_in[0];
    const float* tgt = (const float*)d_in[1];
    const float* sl  = (const float*)d_in[2];
    const float* tl  = (const float*)d_in[3];
    float* out = (float*)d_out;

    cudaFuncSetAttribute(k_mmd, cudaFuncAttributeMaxDynamicSharedMemorySize, SMEM_REQ);

    k_prep<<<128, 256>>>(src, tgt, sl, tl);          // launch 0
    k_mmd<<<NPERS, 512, SMEM_REQ>>>(sl, tl, out);    // launch 1
}